// round 7
// baseline (speedup 1.0000x reference)
#include <cuda_runtime.h>
#include <math.h>
#include <stdint.h>

#define B 4
#define N 2048
#define M 2048
#define C 512
#define H 4
#define DV 128
#define DQK 256

// ---------------------------------------------------------------------------
// scratch (tf32 payloads stored as uint32)
// ---------------------------------------------------------------------------
__device__ __align__(16) uint32_t g_xs[B * N * C];          // x, sigma tf32
__device__ __align__(16) uint32_t g_cs[B * M * C];          // ctx, sigma tf32
__device__ __align__(16) uint32_t g_wq[2 * C * C];          // Wqkv, sigma tf32
__device__ __align__(16) uint32_t g_wp[C * C];              // Wproj, sigma tf32
__device__ __align__(16) uint32_t g_vt[B * H * M * DV];     // V tiles, sigma tf32
__device__ __align__(16) uint32_t g_qn[B * H * N * DQK];    // normed Q, sigma tf32
__device__ __align__(16) uint32_t g_kn[B * H * M * DQK];    // normed K, sigma tf32
__device__ __align__(16) uint32_t g_o [B * N * C];          // attn out, sigma tf32

// ---------------------------------------------------------------------------
// helpers
// ---------------------------------------------------------------------------
__device__ __forceinline__ uint32_t f2tf32(float f) {
    uint32_t u;
    asm("cvt.rna.tf32.f32 %0, %1;" : "=r"(u) : "f"(f));
    return u;
}
__device__ __forceinline__ void mma_tf32(float* c,
                                         uint32_t a0, uint32_t a1, uint32_t a2, uint32_t a3,
                                         uint32_t b0, uint32_t b1) {
    asm volatile(
        "mma.sync.aligned.m16n8k8.row.col.f32.tf32.tf32.f32 "
        "{%0,%1,%2,%3}, {%4,%5,%6,%7}, {%8,%9}, {%0,%1,%2,%3};"
        : "+f"(c[0]), "+f"(c[1]), "+f"(c[2]), "+f"(c[3])
        : "r"(a0), "r"(a1), "r"(a2), "r"(a3), "r"(b0), "r"(b1));
}
__device__ __forceinline__ uint32_t smem_u32(const void* p) {
    uint32_t a;
    asm("{ .reg .u64 t; cvta.to.shared.u64 t, %1; cvt.u32.u64 %0, t; }" : "=r"(a) : "l"(p));
    return a;
}
#define CPA(d, s) asm volatile("cp.async.ca.shared.global [%0], [%1], 16;" :: "r"(d), "l"(s))
#define CP_COMMIT() asm volatile("cp.async.commit_group;" ::: "memory")
#define CP_WAIT0() asm volatile("cp.async.wait_group 0;" ::: "memory")
#define CP_WAIT1() asm volatile("cp.async.wait_group 1;" ::: "memory")

// sigma permutation within an 8-block of k-indices: positions [0,4,1,5,2,6,3,7]
// mma k-pair (tg, tg+4) is a contiguous uint2 at offset 2*tg.
// C-fragment col 2*tg -> pos smap(tg) = (tg>>1)+(tg&1)*4; col 2*tg+1 -> smap+2.

// ---------------------------------------------------------------------------
// Pre-pass A: fp32 rows -> tf32 sigma-interleaved rows (cols multiple of 8)
// ---------------------------------------------------------------------------
__global__ __launch_bounds__(256) void sigma_cvt_kernel(
    const float* __restrict__ src, uint32_t* __restrict__ dst, int nblk8)
{
    int idx = blockIdx.x * 256 + threadIdx.x;
    if (idx >= nblk8) return;
    const float4 v0 = *(const float4*)(src + (size_t)idx * 8);
    const float4 v1 = *(const float4*)(src + (size_t)idx * 8 + 4);
    uint4 u0, u1;
    u0.x = f2tf32(v0.x); u0.y = f2tf32(v1.x); u0.z = f2tf32(v0.y); u0.w = f2tf32(v1.y);
    u1.x = f2tf32(v0.z); u1.y = f2tf32(v1.z); u1.z = f2tf32(v0.w); u1.w = f2tf32(v1.w);
    *(uint4*)(dst + (size_t)idx * 8) = u0;
    *(uint4*)(dst + (size_t)idx * 8 + 4) = u1;
}

// ---------------------------------------------------------------------------
// Pre-pass B: V tiles. g_vt[((b*H+h)*32+mt)*128 + d][64 keys, sigma] (tf32)
// ---------------------------------------------------------------------------
__global__ __launch_bounds__(128) void v_arrange_kernel(const float* __restrict__ ctx)
{
    const int bm = blockIdx.x;             // b*M + m
    const int b = bm >> 11, m = bm & 2047;
    const int i = threadIdx.x;
    const int h = i >> 5, d4 = (i & 31) * 4;
    float4 v = *(const float4*)(ctx + (size_t)bm * C + h * DV + d4);
    const int mt = m >> 6, ml = m & 63;
    const int pos = ((ml >> 3) << 3) + ((ml & 3) * 2 + ((ml >> 2) & 1));
    uint32_t* base = g_vt + ((size_t)((b * H + h) * 32 + mt) * DV) * 64;
    base[(size_t)(d4 + 0) * 64 + pos] = f2tf32(v.x);
    base[(size_t)(d4 + 1) * 64 + pos] = f2tf32(v.y);
    base[(size_t)(d4 + 2) * 64 + pos] = f2tf32(v.z);
    base[(size_t)(d4 + 3) * 64 + pos] = f2tf32(v.w);
}

// ---------------------------------------------------------------------------
// Kernel 1: QKV projection + L2 norm.  CTA = 64 rows x 256 cols (one head).
// 512 threads / 16 warps: wy = wid&1 (32 rows), wx = wid>>1 (32 cols).
// k = 512 in 8 chunks, cp.async double-buffered, sigma-tf32 operands.
// ---------------------------------------------------------------------------
#define QKV_XB(i)  ((i) * 17408)             // 2 x 64 x 68 x 4
#define QKV_WB(i)  (34816 + (i) * 69632)     // 2 x 256 x 68 x 4
#define QKV_SSOFF  174080                    // 8 x 64 floats = 2048 B
#define QKV_SMEM   176128

__global__ __launch_bounds__(512) void qkv3_kernel(const float* __restrict__ radius)
{
    extern __shared__ char smem[];
    const uint32_t sbase = smem_u32(smem);
    float* ssPart = (float*)(smem + QKV_SSOFF);

    const int z  = blockIdx.z;
    const uint32_t* Asrc = z ? g_cs : g_xs;
    uint32_t* dst = z ? g_kn : g_qn;
    const int h  = blockIdx.y;
    const int r0 = blockIdx.x * 64;
    const int tid = threadIdx.x;
    const int wid = tid >> 5, lane = tid & 31;
    const int rq = lane >> 2, tg = lane & 3;
    const int wy = wid & 1, wx = wid >> 1;     // wx 0..7
    const int qr = wy * 32 + rq;

    const uint32_t* asrc_base = Asrc + (size_t)r0 * C;
    const uint32_t* wsrc_base = g_wq + (size_t)(h * 256) * C;

    auto issue = [&](int kc, int bi) {
        const uint32_t xd = sbase + QKV_XB(bi);
        const uint32_t wd = sbase + QKV_WB(bi);
#pragma unroll
        for (int t = 0; t < 2; t++) {
            int i = tid + t * 512;
            int r = i >> 4, c16 = i & 15;                  // 64 rows x 16 chunks
            CPA(xd + (uint32_t)(r * 272 + c16 * 16),
                asrc_base + (size_t)r * C + kc * 64 + c16 * 4);
        }
#pragma unroll
        for (int t = 0; t < 8; t++) {
            int i = tid + t * 512;
            int r = i >> 4, c16 = i & 15;                  // 256 rows x 16 chunks
            CPA(wd + (uint32_t)(r * 272 + c16 * 16),
                wsrc_base + (size_t)r * C + kc * 64 + c16 * 4);
        }
        CP_COMMIT();
    };

    float acc[4][2][4];
#pragma unroll
    for (int a = 0; a < 4; a++)
#pragma unroll
        for (int m2 = 0; m2 < 2; m2++)
#pragma unroll
            for (int j = 0; j < 4; j++) acc[a][m2][j] = 0.f;

    issue(0, 0);
    for (int kc = 0; kc < 8; kc++) {
        if (kc < 7) issue(kc + 1, (kc + 1) & 1);
        if (kc < 7) { CP_WAIT1(); } else { CP_WAIT0(); }
        __syncthreads();
        const uint32_t* Xu = (const uint32_t*)(smem + QKV_XB(kc & 1));
        const uint32_t* Wu = (const uint32_t*)(smem + QKV_WB(kc & 1));
#pragma unroll
        for (int ks = 0; ks < 8; ks++) {
            const int ko = ks * 8 + 2 * tg;
            uint2 aA = *(const uint2*)(Xu + qr * 68 + ko);
            uint2 aB = *(const uint2*)(Xu + (qr + 8) * 68 + ko);
            uint2 aC = *(const uint2*)(Xu + (qr + 16) * 68 + ko);
            uint2 aD = *(const uint2*)(Xu + (qr + 24) * 68 + ko);
#pragma unroll
            for (int nt = 0; nt < 4; nt++) {
                uint2 bb = *(const uint2*)(Wu + (wx * 32 + nt * 8 + rq) * 68 + ko);
                mma_tf32(acc[nt][0], aA.x, aB.x, aA.y, aB.y, bb.x, bb.y);
                mma_tf32(acc[nt][1], aC.x, aD.x, aC.y, aD.y, bb.x, bb.y);
            }
        }
        __syncthreads();
    }

    // per-row sum of squares (rows qr, qr+8, qr+16, qr+24)
    float ss[4] = {0.f, 0.f, 0.f, 0.f};
#pragma unroll
    for (int nt = 0; nt < 4; nt++) {
        ss[0] += acc[nt][0][0] * acc[nt][0][0] + acc[nt][0][1] * acc[nt][0][1];
        ss[1] += acc[nt][0][2] * acc[nt][0][2] + acc[nt][0][3] * acc[nt][0][3];
        ss[2] += acc[nt][1][0] * acc[nt][1][0] + acc[nt][1][1] * acc[nt][1][1];
        ss[3] += acc[nt][1][2] * acc[nt][1][2] + acc[nt][1][3] * acc[nt][1][3];
    }
#pragma unroll
    for (int o = 1; o < 4; o <<= 1)
#pragma unroll
        for (int r = 0; r < 4; r++) ss[r] += __shfl_xor_sync(0xffffffffu, ss[r], o);
    if (tg == 0) {
#pragma unroll
        for (int r = 0; r < 4; r++) ssPart[wx * 64 + qr + r * 8] = ss[r];
    }
    __syncthreads();

    const float rad = radius[h];
    const int smap = (tg >> 1) + (tg & 1) * 4;
#pragma unroll
    for (int r = 0; r < 4; r++) {
        const int row = qr + r * 8;
        float tot = 0.f;
#pragma unroll
        for (int g = 0; g < 8; g++) tot += ssPart[g * 64 + row];
        float sc = rad / fmaxf(sqrtf(tot), 1e-12f);
        const int gr = r0 + row;
        const int bb = gr >> 11, nn = gr & 2047;
        uint32_t* out = dst + ((size_t)(bb * H + h) * N + nn) * DQK;
#pragma unroll
        for (int nt = 0; nt < 4; nt++) {
            const int m2 = r >> 1, lo = (r & 1) * 2;
            const int pos = wx * 32 + nt * 8 + smap;
            out[pos]     = f2tf32(acc[nt][m2][lo + 0] * sc);
            out[pos + 2] = f2tf32(acc[nt][m2][lo + 1] * sc);
        }
    }
}

// ---------------------------------------------------------------------------
// Kernel 2: attention.  CTA = 64 queries of (b,h); 64-key tiles, 32 iters.
// 512 threads / 16 warps.  S: 4x4 grid (m16 x n16).  PV: 2x8 grid (m32 x n16).
// One-pass softmax, static shift sqrt(128).  cp.async: V double-buffered,
// K prefetch overlapped with PV.
// ---------------------------------------------------------------------------
#define ATT_QO   0                      // 64 x 260 x 4 = 66560
#define ATT_KO   66560                  // 64 x 260 x 4
#define ATT_VO   133120                 // 2 x (128 x 68 x 4) = 69632
#define ATT_PO   202752                 // 64 x 68 x 4 = 17408
#define ATT_RSO  220160                 // 4 x 64 floats = 1024
#define ATT_INVO 221184                 // 64 floats
#define ATT_SMEM 221440

__global__ __launch_bounds__(512) void attn3_kernel()
{
    extern __shared__ char smem[];
    const uint32_t sbase = smem_u32(smem);
    uint32_t* Qu = (uint32_t*)(smem + ATT_QO);
    uint32_t* Ku = (uint32_t*)(smem + ATT_KO);
    uint32_t* Pu = (uint32_t*)(smem + ATT_PO);
    float* rsPart = (float*)(smem + ATT_RSO);
    float* invS   = (float*)(smem + ATT_INVO);

    const int nt_blk = blockIdx.x;
    const int h = blockIdx.y, b = blockIdx.z;
    const int tid = threadIdx.x;
    const int wid = tid >> 5, lane = tid & 31;
    const int rq = lane >> 2, tg = lane & 3;
    // S-phase mapping: 4 row groups x 4 col groups
    const int qrS = (wid & 3) * 16 + rq;
    const int wxS = wid >> 2;                 // 0..3, 16 cols each
    // PV-phase mapping: 2 row groups x 8 col groups
    const int qrP = (wid & 1) * 32 + rq;
    const int wxP = wid >> 1;                 // 0..7, 16 cols each

    const uint32_t* qsrc = g_qn + ((size_t)(b * H + h) * N + nt_blk * 64) * DQK;
    const uint32_t* ksrc = g_kn + ((size_t)(b * H + h) * M) * DQK;
    const uint32_t* vsrc = g_vt + ((size_t)(b * H + h) * 32) * DV * 64;

    auto issue_k = [&](int mt) {
        const uint32_t kd = sbase + ATT_KO;
        const uint32_t* s = ksrc + (size_t)mt * 64 * DQK;
#pragma unroll
        for (int t = 0; t < 8; t++) {
            int i = tid + t * 512;
            int r = i >> 6, c16 = i & 63;               // 64 rows x 64 chunks
            CPA(kd + (uint32_t)(r * 1040 + c16 * 16), s + (size_t)r * DQK + c16 * 4);
        }
        CP_COMMIT();
    };
    auto issue_v = [&](int mt, int bi) {
        const uint32_t vd = sbase + ATT_VO + bi * 34816;
        const uint32_t* s = vsrc + (size_t)mt * DV * 64;
#pragma unroll
        for (int t = 0; t < 4; t++) {
            int i = tid + t * 512;
            int r = i >> 4, c16 = i & 15;               // 128 rows x 16 chunks
            CPA(vd + (uint32_t)(r * 272 + c16 * 16), s + (size_t)r * 64 + c16 * 4);
        }
        CP_COMMIT();
    };

    // prologue: Q + K0 + V0
    {
        const uint32_t qd = sbase + ATT_QO;
#pragma unroll
        for (int t = 0; t < 8; t++) {
            int i = tid + t * 512;
            int r = i >> 6, c16 = i & 63;
            CPA(qd + (uint32_t)(r * 1040 + c16 * 16), qsrc + (size_t)r * DQK + c16 * 4);
        }
        CP_COMMIT();
    }
    issue_k(0);
    issue_v(0, 0);
    CP_WAIT0();
    __syncthreads();

    float o_acc[2][2][4];
#pragma unroll
    for (int a = 0; a < 2; a++)
#pragma unroll
        for (int m2 = 0; m2 < 2; m2++)
#pragma unroll
            for (int j = 0; j < 4; j++) o_acc[a][m2][j] = 0.f;
    float rsum0 = 0.f, rsum1 = 0.f;

    const float SCALE = 0.08838834764831845f;  // 1/sqrt(128)
    const float SMAX  = 11.313708498984761f;   // sqrt(128)
    const int smap = (tg >> 1) + (tg & 1) * 4;

    for (int mt = 0; mt < 32; mt++) {
        const int cur = mt & 1;
        if (mt + 1 < 32) issue_v(mt + 1, cur ^ 1);

        // ---- S = Q K^T (m16n16 per warp, k = 256) ----
        float s[2][4];
#pragma unroll
        for (int a = 0; a < 2; a++)
#pragma unroll
            for (int j = 0; j < 4; j++) s[a][j] = 0.f;
#pragma unroll 8
        for (int ks = 0; ks < 32; ks++) {
            const int ko = ks * 8 + 2 * tg;
            uint2 aA = *(const uint2*)(Qu + qrS * 260 + ko);
            uint2 aB = *(const uint2*)(Qu + (qrS + 8) * 260 + ko);
#pragma unroll
            for (int nt = 0; nt < 2; nt++) {
                uint2 bb = *(const uint2*)(Ku + (wxS * 16 + nt * 8 + rq) * 260 + ko);
                mma_tf32(s[nt], aA.x, aB.x, aA.y, aB.y, bb.x, bb.y);
            }
        }

        // ---- softmax epilogue -> P (tf32 sigma) ----
#pragma unroll
        for (int nt = 0; nt < 2; nt++) {
            float p0 = __expf(fmaf(s[nt][0], SCALE, -SMAX));
            float p1 = __expf(fmaf(s[nt][1], SCALE, -SMAX));
            float p2 = __expf(fmaf(s[nt][2], SCALE, -SMAX));
            float p3 = __expf(fmaf(s[nt][3], SCALE, -SMAX));
            rsum0 += p0 + p1;
            rsum1 += p2 + p3;
            const int pos = wxS * 16 + nt * 8 + smap;
            Pu[qrS * 68 + pos]           = f2tf32(p0);
            Pu[qrS * 68 + pos + 2]       = f2tf32(p1);
            Pu[(qrS + 8) * 68 + pos]     = f2tf32(p2);
            Pu[(qrS + 8) * 68 + pos + 2] = f2tf32(p3);
        }
        __syncthreads();                       // S done (K free), P visible

        if (mt + 1 < 32) issue_k(mt + 1);      // overlaps PV

        // ---- O += P V (m32n16 per warp, k = 64) ----
        const uint32_t* Vu = (const uint32_t*)(smem + ATT_VO + cur * 34816);
#pragma unroll
        for (int ks = 0; ks < 8; ks++) {
            const int ko = ks * 8 + 2 * tg;
            uint2 pA = *(const uint2*)(Pu + qrP * 68 + ko);
            uint2 pB = *(const uint2*)(Pu + (qrP + 8) * 68 + ko);
            uint2 pC = *(const uint2*)(Pu + (qrP + 16) * 68 + ko);
            uint2 pD = *(const uint2*)(Pu + (qrP + 24) * 68 + ko);
#pragma unroll
            for (int nt = 0; nt < 2; nt++) {
                uint2 vv = *(const uint2*)(Vu + (wxP * 16 + nt * 8 + rq) * 68 + ko);
                mma_tf32(o_acc[nt][0], pA.x, pB.x, pA.y, pB.y, vv.x, vv.y);
                mma_tf32(o_acc[nt][1], pC.x, pD.x, pC.y, pD.y, vv.x, vv.y);
            }
        }
        CP_WAIT0();
        __syncthreads();
    }

    // ---- row sums -> 1/sum ----
#pragma unroll
    for (int o = 1; o < 4; o <<= 1) {
        rsum0 += __shfl_xor_sync(0xffffffffu, rsum0, o);
        rsum1 += __shfl_xor_sync(0xffffffffu, rsum1, o);
    }
    if (tg == 0) {
        rsPart[wxS * 64 + qrS] = rsum0;
        rsPart[wxS * 64 + qrS + 8] = rsum1;
    }
    __syncthreads();
    if (tid < 64)
        invS[tid] = 1.f / (rsPart[tid] + rsPart[64 + tid] +
                           rsPart[128 + tid] + rsPart[192 + tid]);
    __syncthreads();

    // ---- write O (tf32 sigma layout for proj) ----
    const float i0 = invS[qrP], i1 = invS[qrP + 8], i2 = invS[qrP + 16], i3 = invS[qrP + 24];
    uint32_t* o0 = g_o + ((size_t)(b * N + nt_blk * 64 + qrP)) * C + h * DV;
    uint32_t* o1 = o0 + (size_t)8 * C;
    uint32_t* o2 = o0 + (size_t)16 * C;
    uint32_t* o3 = o0 + (size_t)24 * C;
#pragma unroll
    for (int nt = 0; nt < 2; nt++) {
        const int pos = wxP * 16 + nt * 8 + smap;
        o0[pos]     = f2tf32(o_acc[nt][0][0] * i0);
        o0[pos + 2] = f2tf32(o_acc[nt][0][1] * i0);
        o1[pos]     = f2tf32(o_acc[nt][0][2] * i1);
        o1[pos + 2] = f2tf32(o_acc[nt][0][3] * i1);
        o2[pos]     = f2tf32(o_acc[nt][1][0] * i2);
        o2[pos + 2] = f2tf32(o_acc[nt][1][1] * i2);
        o3[pos]     = f2tf32(o_acc[nt][1][2] * i3);
        o3[pos + 2] = f2tf32(o_acc[nt][1][3] * i3);
    }
}

// ---------------------------------------------------------------------------
// Kernel 3: output projection, 512 threads, same structure as qkv (no norm).
// CTA 64 rows x 256 cols; out is plain fp32.
// ---------------------------------------------------------------------------
__global__ __launch_bounds__(512) void proj3_kernel(float* __restrict__ out)
{
    extern __shared__ char smem[];
    const uint32_t sbase = smem_u32(smem);

    const int r0 = blockIdx.x * 64;
    const int c0 = blockIdx.y * 256;
    const int tid = threadIdx.x;
    const int wid = tid >> 5, lane = tid & 31;
    const int rq = lane >> 2, tg = lane & 3;
    const int wy = wid & 1, wx = wid >> 1;
    const int qr = wy * 32 + rq;

    const uint32_t* asrc_base = g_o + (size_t)r0 * C;
    const uint32_t* wsrc_base = g_wp + (size_t)c0 * C;

    auto issue = [&](int kc, int bi) {
        const uint32_t xd = sbase + QKV_XB(bi);
        const uint32_t wd = sbase + QKV_WB(bi);
#pragma unroll
        for (int t = 0; t < 2; t++) {
            int i = tid + t * 512;
            int r = i >> 4, c16 = i & 15;
            CPA(xd + (uint32_t)(r * 272 + c16 * 16),
                asrc_base + (size_t)r * C + kc * 64 + c16 * 4);
        }
#pragma unroll
        for (int t = 0; t < 8; t++) {
            int i = tid + t * 512;
            int r = i >> 4, c16 = i & 15;
            CPA(wd + (uint32_t)(r * 272 + c16 * 16),
                wsrc_base + (size_t)r * C + kc * 64 + c16 * 4);
        }
        CP_COMMIT();
    };

    float acc[4][2][4];
#pragma unroll
    for (int a = 0; a < 4; a++)
#pragma unroll
        for (int m2 = 0; m2 < 2; m2++)
#pragma unroll
            for (int j = 0; j < 4; j++) acc[a][m2][j] = 0.f;

    issue(0, 0);
    for (int kc = 0; kc < 8; kc++) {
        if (kc < 7) issue(kc + 1, (kc + 1) & 1);
        if (kc < 7) { CP_WAIT1(); } else { CP_WAIT0(); }
        __syncthreads();
        const uint32_t* Xu = (const uint32_t*)(smem + QKV_XB(kc & 1));
        const uint32_t* Wu = (const uint32_t*)(smem + QKV_WB(kc & 1));
#pragma unroll
        for (int ks = 0; ks < 8; ks++) {
            const int ko = ks * 8 + 2 * tg;
            uint2 aA = *(const uint2*)(Xu + qr * 68 + ko);
            uint2 aB = *(const uint2*)(Xu + (qr + 8) * 68 + ko);
            uint2 aC = *(const uint2*)(Xu + (qr + 16) * 68 + ko);
            uint2 aD = *(const uint2*)(Xu + (qr + 24) * 68 + ko);
#pragma unroll
            for (int nt = 0; nt < 4; nt++) {
                uint2 bb = *(const uint2*)(Wu + (wx * 32 + nt * 8 + rq) * 68 + ko);
                mma_tf32(acc[nt][0], aA.x, aB.x, aA.y, aB.y, bb.x, bb.y);
                mma_tf32(acc[nt][1], aC.x, aD.x, aC.y, aD.y, bb.x, bb.y);
            }
        }
        __syncthreads();
    }

#pragma unroll
    for (int r = 0; r < 4; r++) {
        const int row = qr + r * 8;
        float* o = out + (size_t)(r0 + row) * C + c0;
        const int m2 = r >> 1, lo = (r & 1) * 2;
#pragma unroll
        for (int nt = 0; nt < 4; nt++) {
            const int col = wx * 32 + nt * 8 + 2 * tg;
            *(float2*)(o + col) = make_float2(acc[nt][m2][lo + 0], acc[nt][m2][lo + 1]);
        }
    }
}

// ---------------------------------------------------------------------------
extern "C" void kernel_launch(void* const* d_in, const int* in_sizes, int n_in,
                              void* d_out, int out_size)
{
    const float* x      = (const float*)d_in[0];
    const float* ctx    = (const float*)d_in[1];
    const float* Wqkv   = (const float*)d_in[2];
    const float* Wproj  = (const float*)d_in[3];
    const float* radius = (const float*)d_in[4];
    float* out = (float*)d_out;
    (void)in_sizes; (void)n_in; (void)out_size;

    cudaFuncSetAttribute(qkv3_kernel, cudaFuncAttributeMaxDynamicSharedMemorySize, QKV_SMEM);
    cudaFuncSetAttribute(attn3_kernel, cudaFuncAttributeMaxDynamicSharedMemorySize, ATT_SMEM);
    cudaFuncSetAttribute(proj3_kernel, cudaFuncAttributeMaxDynamicSharedMemorySize, QKV_SMEM);

    uint32_t* d_xs; cudaGetSymbolAddress((void**)&d_xs, g_xs);
    uint32_t* d_cs; cudaGetSymbolAddress((void**)&d_cs, g_cs);
    uint32_t* d_wq; cudaGetSymbolAddress((void**)&d_wq, g_wq);
    uint32_t* d_wp; cudaGetSymbolAddress((void**)&d_wp, g_wp);

    // pre-pass conversions
    sigma_cvt_kernel<<<(B * N * C / 8) / 256, 256>>>(x, d_xs, B * N * C / 8);
    sigma_cvt_kernel<<<(B * M * C / 8) / 256, 256>>>(ctx, d_cs, B * M * C / 8);
    sigma_cvt_kernel<<<(2 * C * C / 8) / 256, 256>>>(Wqkv, d_wq, 2 * C * C / 8);
    sigma_cvt_kernel<<<(C * C / 8) / 256, 256>>>(Wproj, d_wp, C * C / 8);
    v_arrange_kernel<<<B * M, 128>>>(ctx);

    // 1) QKV + per-head L2 norm
    qkv3_kernel<<<dim3((B * N) / 64, H, 2), 512, QKV_SMEM>>>(radius);

    // 2) attention
    attn3_kernel<<<dim3(N / 64, H, B), 512, ATT_SMEM>>>();

    // 3) output projection
    proj3_kernel<<<dim3((B * N) / 64, C / 256), 512, QKV_SMEM>>>(out);
}

// round 8
// speedup vs baseline: 1.1128x; 1.1128x over previous
#include <cuda_runtime.h>
#include <math.h>
#include <stdint.h>

#define B 4
#define N 2048
#define M 2048
#define C 512
#define H 4
#define DV 128
#define DQK 256

// ---------------------------------------------------------------------------
// scratch
// ---------------------------------------------------------------------------
__device__ __align__(16) uint32_t g_vt[B * H * M * DV];     // V^T tiles, sigma tf32
__device__ __align__(16) uint32_t g_qn[B * H * N * DQK];    // normed Q, sigma tf32
__device__ __align__(16) uint32_t g_kn[B * H * M * DQK];    // normed K, sigma tf32
__device__ __align__(16) uint32_t g_o [B * N * C];          // attn out, sigma tf32

// ---------------------------------------------------------------------------
// helpers
// ---------------------------------------------------------------------------
__device__ __forceinline__ uint32_t f2tf32(float f) {
    uint32_t u;
    asm("cvt.rna.tf32.f32 %0, %1;" : "=r"(u) : "f"(f));
    return u;
}
__device__ __forceinline__ void mma_tf32(float* c,
                                         uint32_t a0, uint32_t a1, uint32_t a2, uint32_t a3,
                                         uint32_t b0, uint32_t b1) {
    asm volatile(
        "mma.sync.aligned.m16n8k8.row.col.f32.tf32.tf32.f32 "
        "{%0,%1,%2,%3}, {%4,%5,%6,%7}, {%8,%9}, {%0,%1,%2,%3};"
        : "+f"(c[0]), "+f"(c[1]), "+f"(c[2]), "+f"(c[3])
        : "r"(a0), "r"(a1), "r"(a2), "r"(a3), "r"(b0), "r"(b1));
}

// sigma permutation within each 8-block of k-indices: pos(j) = (j&3)*2 + (j>>2)
// -> the mma k-pair (base+tg, base+tg+4) is a contiguous uint2 at base + 2*tg.
// C-fragment col 2*tg lands at smap(tg) = (tg>>1)+(tg&1)*4; col 2*tg+1 at smap+2.

// cvt fp32 float4 (cols cc..cc+3, cc multiple of 4) -> sigma positions in row
__device__ __forceinline__ void st_sigma4(uint32_t* row, int cc, float4 v) {
    uint32_t* p = row + (cc & ~7) + ((cc & 4) ? 1 : 0);
    p[0] = f2tf32(v.x); p[2] = f2tf32(v.y); p[4] = f2tf32(v.z); p[6] = f2tf32(v.w);
}

// ---------------------------------------------------------------------------
// Pre-pass: V^T tiles. g_vt[((b*H+h)*32+mt)*128 + d][64 keys, sigma] (tf32)
// ---------------------------------------------------------------------------
__global__ __launch_bounds__(128) void v_arrange_kernel(const float* __restrict__ ctx)
{
    const int bm = blockIdx.x;             // b*M + m
    const int b = bm >> 11, m = bm & 2047;
    const int i = threadIdx.x;
    const int h = i >> 5, d4 = (i & 31) * 4;
    float4 v = *(const float4*)(ctx + (size_t)bm * C + h * DV + d4);
    const int mt = m >> 6, ml = m & 63;
    const int pos = ((ml >> 3) << 3) + ((ml & 3) * 2 + ((ml >> 2) & 1));
    uint32_t* base = g_vt + ((size_t)((b * H + h) * 32 + mt) * DV) * 64;
    base[(size_t)(d4 + 0) * 64 + pos] = f2tf32(v.x);
    base[(size_t)(d4 + 1) * 64 + pos] = f2tf32(v.y);
    base[(size_t)(d4 + 2) * 64 + pos] = f2tf32(v.z);
    base[(size_t)(d4 + 3) * 64 + pos] = f2tf32(v.w);
}

// ---------------------------------------------------------------------------
// Kernel 1: QKV projection + L2 norm.  CTA = 64 rows x 256 cols (one head).
// 256 threads / 8 warps: wy = wid&1 (32 rows m32), wcq = wid>>1 (64 cols n64).
// k = 512 in 8 chunks of 64, synchronous loads, cvt+sigma at smem store.
// Output written as tf32 sigma (k-dim of attention).
// ---------------------------------------------------------------------------
#define QKV_XS   0                         // 64*68*4  = 17408
#define QKV_WS   17408                     // 256*68*4 = 69632
#define QKV_SS   87040                     // 4*64 floats
#define QKV_SMEM 88064

__global__ __launch_bounds__(256) void qkv4_kernel(
    const float* __restrict__ x, const float* __restrict__ ctx,
    const float* __restrict__ Wqkv, const float* __restrict__ radius)
{
    extern __shared__ char smem[];
    uint32_t* Xu = (uint32_t*)(smem + QKV_XS);
    uint32_t* Wu = (uint32_t*)(smem + QKV_WS);
    float* ssPart = (float*)(smem + QKV_SS);

    const float* src = blockIdx.z ? ctx : x;
    uint32_t* dst = blockIdx.z ? g_kn : g_qn;
    const int h  = blockIdx.y;
    const int r0 = blockIdx.x * 64;
    const int tid = threadIdx.x;
    const int wid = tid >> 5, lane = tid & 31;
    const int rq = lane >> 2, tg = lane & 3;
    const int wy = wid & 1, wcq = wid >> 1;      // wcq 0..3
    const int qr = wy * 32 + rq;

    float acc[8][2][4];
#pragma unroll
    for (int a = 0; a < 8; a++)
#pragma unroll
        for (int m2 = 0; m2 < 2; m2++)
#pragma unroll
            for (int j = 0; j < 4; j++) acc[a][m2][j] = 0.f;

    for (int kc = 0; kc < 8; kc++) {
        // X chunk 64 x 64 (fp32 -> tf32 sigma)
#pragma unroll
        for (int t = 0; t < 4; t++) {
            int i = tid + t * 256;
            int r = i >> 4, cc = (i & 15) * 4;
            float4 v = *(const float4*)(src + (size_t)(r0 + r) * C + kc * 64 + cc);
            st_sigma4(Xu + r * 68, cc, v);
        }
        // W chunk 256 x 64
#pragma unroll
        for (int t = 0; t < 16; t++) {
            int i = tid + t * 256;
            int r = i >> 4, cc = (i & 15) * 4;
            float4 v = *(const float4*)(Wqkv + (size_t)(h * 256 + r) * C + kc * 64 + cc);
            st_sigma4(Wu + r * 68, cc, v);
        }
        __syncthreads();
#pragma unroll
        for (int ks = 0; ks < 8; ks++) {
            const int ko = ks * 8 + 2 * tg;
            uint2 aA = *(const uint2*)(Xu + qr * 68 + ko);
            uint2 aB = *(const uint2*)(Xu + (qr + 8) * 68 + ko);
            uint2 aC = *(const uint2*)(Xu + (qr + 16) * 68 + ko);
            uint2 aD = *(const uint2*)(Xu + (qr + 24) * 68 + ko);
#pragma unroll
            for (int nt = 0; nt < 8; nt++) {
                uint2 bb = *(const uint2*)(Wu + (wcq * 64 + nt * 8 + rq) * 68 + ko);
                mma_tf32(acc[nt][0], aA.x, aB.x, aA.y, aB.y, bb.x, bb.y);
                mma_tf32(acc[nt][1], aC.x, aD.x, aC.y, aD.y, bb.x, bb.y);
            }
        }
        __syncthreads();
    }

    // per-row sum of squares (rows qr, qr+8, qr+16, qr+24)
    float ss[4] = {0.f, 0.f, 0.f, 0.f};
#pragma unroll
    for (int nt = 0; nt < 8; nt++) {
        ss[0] += acc[nt][0][0] * acc[nt][0][0] + acc[nt][0][1] * acc[nt][0][1];
        ss[1] += acc[nt][0][2] * acc[nt][0][2] + acc[nt][0][3] * acc[nt][0][3];
        ss[2] += acc[nt][1][0] * acc[nt][1][0] + acc[nt][1][1] * acc[nt][1][1];
        ss[3] += acc[nt][1][2] * acc[nt][1][2] + acc[nt][1][3] * acc[nt][1][3];
    }
#pragma unroll
    for (int o = 1; o < 4; o <<= 1)
#pragma unroll
        for (int r = 0; r < 4; r++) ss[r] += __shfl_xor_sync(0xffffffffu, ss[r], o);
    if (tg == 0) {
#pragma unroll
        for (int r = 0; r < 4; r++) ssPart[wcq * 64 + qr + r * 8] = ss[r];
    }
    __syncthreads();

    const float rad = radius[h];
    const int smap = (tg >> 1) + (tg & 1) * 4;
#pragma unroll
    for (int r = 0; r < 4; r++) {
        const int row = qr + r * 8;
        float tot = ssPart[row] + ssPart[64 + row] + ssPart[128 + row] + ssPart[192 + row];
        float sc = rad / fmaxf(sqrtf(tot), 1e-12f);
        const int gr = r0 + row;
        const int bb = gr >> 11, nn = gr & 2047;
        uint32_t* out = dst + ((size_t)(bb * H + h) * N + nn) * DQK;
        const int m2 = r >> 1, lo = (r & 1) * 2;
#pragma unroll
        for (int nt = 0; nt < 8; nt++) {
            const int pos = wcq * 64 + nt * 8 + smap;
            out[pos]     = f2tf32(acc[nt][m2][lo + 0] * sc);
            out[pos + 2] = f2tf32(acc[nt][m2][lo + 1] * sc);
        }
    }
}

// ---------------------------------------------------------------------------
// Kernel 2: attention.  CTA = 64 queries of (b,h); 64-key tiles, 32 iters.
// 256 threads / 8 warps.  S: 4x2 (m16 x n32).  PV: 2x4 (m32 x n32).
// One-pass softmax, static shift sqrt(128).  Synchronous uint4 tile copies
// (Q/K/V already tf32 sigma in global).
// ---------------------------------------------------------------------------
#define ATT_QO   0                      // 64 x 260 x 4 = 66560
#define ATT_KO   66560                  // 64 x 260 x 4 = 66560
#define ATT_VO   133120                 // 128 x 68 x 4 = 34816
#define ATT_PO   167936                 // 64 x 68 x 4  = 17408
#define ATT_RSO  185344                 // 2 x 64 floats = 512
#define ATT_INVO 185856                 // 64 floats
#define ATT_SMEM 186112

__global__ __launch_bounds__(256) void attn4_kernel()
{
    extern __shared__ char smem[];
    uint32_t* Qu = (uint32_t*)(smem + ATT_QO);
    uint32_t* Ku = (uint32_t*)(smem + ATT_KO);
    uint32_t* Vu = (uint32_t*)(smem + ATT_VO);
    uint32_t* Pu = (uint32_t*)(smem + ATT_PO);
    float* rsPart = (float*)(smem + ATT_RSO);
    float* invS   = (float*)(smem + ATT_INVO);

    const int nt_blk = blockIdx.x;
    const int h = blockIdx.y, b = blockIdx.z;
    const int tid = threadIdx.x;
    const int wid = tid >> 5, lane = tid & 31;
    const int rq = lane >> 2, tg = lane & 3;
    // S-phase: 4 row groups (m16) x 2 col groups (n32)
    const int qrS = (wid & 3) * 16 + rq;
    const int wcS = wid >> 2;                 // 0..1
    // PV-phase: 2 row groups (m32) x 4 col groups (n32)
    const int qrP = (wid & 1) * 32 + rq;
    const int wcP = wid >> 1;                 // 0..3

    const uint32_t* qsrc = g_qn + ((size_t)(b * H + h) * N + nt_blk * 64) * DQK;
    const uint32_t* ksrc = g_kn + ((size_t)(b * H + h) * M) * DQK;
    const uint32_t* vsrc = g_vt + ((size_t)(b * H + h) * 32) * DV * 64;

    // Q tile once (sigma tf32 copy)
#pragma unroll
    for (int t = 0; t < 16; t++) {
        int i = tid + t * 256;
        int r = i >> 6, c16 = i & 63;
        *(uint4*)(Qu + r * 260 + c16 * 4) = *(const uint4*)(qsrc + (size_t)r * DQK + c16 * 4);
    }

    float o_acc[4][2][4];
#pragma unroll
    for (int a = 0; a < 4; a++)
#pragma unroll
        for (int m2 = 0; m2 < 2; m2++)
#pragma unroll
            for (int j = 0; j < 4; j++) o_acc[a][m2][j] = 0.f;
    float rsum0 = 0.f, rsum1 = 0.f;

    const float SCALE = 0.08838834764831845f;  // 1/sqrt(128)
    const float SMAX  = 11.313708498984761f;   // sqrt(128)
    const int smap = (tg >> 1) + (tg & 1) * 4;

    for (int mt = 0; mt < 32; mt++) {
        __syncthreads();                       // prev PV done with V/P; K free
        // K tile 64 x 256 (sigma copy)
        {
            const uint32_t* s = ksrc + (size_t)mt * 64 * DQK;
#pragma unroll
            for (int t = 0; t < 16; t++) {
                int i = tid + t * 256;
                int r = i >> 6, c16 = i & 63;
                *(uint4*)(Ku + r * 260 + c16 * 4) = *(const uint4*)(s + (size_t)r * DQK + c16 * 4);
            }
        }
        // V^T tile 128 x 64 (sigma copy)
        {
            const uint32_t* s = vsrc + (size_t)mt * DV * 64;
#pragma unroll
            for (int t = 0; t < 8; t++) {
                int i = tid + t * 256;
                int r = i >> 4, c16 = i & 15;
                *(uint4*)(Vu + r * 68 + c16 * 4) = *(const uint4*)(s + (size_t)r * 64 + c16 * 4);
            }
        }
        __syncthreads();

        // ---- S = Q K^T (m16n32 per warp, k = 256) ----
        float s[4][4];
#pragma unroll
        for (int a = 0; a < 4; a++)
#pragma unroll
            for (int j = 0; j < 4; j++) s[a][j] = 0.f;
#pragma unroll 4
        for (int ks = 0; ks < 32; ks++) {
            const int ko = ks * 8 + 2 * tg;
            uint2 aA = *(const uint2*)(Qu + qrS * 260 + ko);
            uint2 aB = *(const uint2*)(Qu + (qrS + 8) * 260 + ko);
#pragma unroll
            for (int nt = 0; nt < 4; nt++) {
                uint2 bb = *(const uint2*)(Ku + (wcS * 32 + nt * 8 + rq) * 260 + ko);
                mma_tf32(s[nt], aA.x, aB.x, aA.y, aB.y, bb.x, bb.y);
            }
        }

        // ---- softmax epilogue -> P (tf32 sigma) ----
#pragma unroll
        for (int nt = 0; nt < 4; nt++) {
            float p0 = __expf(fmaf(s[nt][0], SCALE, -SMAX));
            float p1 = __expf(fmaf(s[nt][1], SCALE, -SMAX));
            float p2 = __expf(fmaf(s[nt][2], SCALE, -SMAX));
            float p3 = __expf(fmaf(s[nt][3], SCALE, -SMAX));
            rsum0 += p0 + p1;
            rsum1 += p2 + p3;
            const int pos = wcS * 32 + nt * 8 + smap;
            Pu[qrS * 68 + pos]           = f2tf32(p0);
            Pu[qrS * 68 + pos + 2]       = f2tf32(p1);
            Pu[(qrS + 8) * 68 + pos]     = f2tf32(p2);
            Pu[(qrS + 8) * 68 + pos + 2] = f2tf32(p3);
        }
        __syncthreads();

        // ---- O += P V (m32n32 per warp, k = 64) ----
#pragma unroll
        for (int ks = 0; ks < 8; ks++) {
            const int ko = ks * 8 + 2 * tg;
            uint2 pA = *(const uint2*)(Pu + qrP * 68 + ko);
            uint2 pB = *(const uint2*)(Pu + (qrP + 8) * 68 + ko);
            uint2 pC = *(const uint2*)(Pu + (qrP + 16) * 68 + ko);
            uint2 pD = *(const uint2*)(Pu + (qrP + 24) * 68 + ko);
#pragma unroll
            for (int nt = 0; nt < 4; nt++) {
                uint2 vv = *(const uint2*)(Vu + (wcP * 32 + nt * 8 + rq) * 68 + ko);
                mma_tf32(o_acc[nt][0], pA.x, pB.x, pA.y, pB.y, vv.x, vv.y);
                mma_tf32(o_acc[nt][1], pC.x, pD.x, pC.y, pD.y, vv.x, vv.y);
            }
        }
    }

    // ---- row sums -> 1/sum ----
#pragma unroll
    for (int o = 1; o < 4; o <<= 1) {
        rsum0 += __shfl_xor_sync(0xffffffffu, rsum0, o);
        rsum1 += __shfl_xor_sync(0xffffffffu, rsum1, o);
    }
    __syncthreads();
    if (tg == 0) {
        rsPart[wcS * 64 + qrS] = rsum0;
        rsPart[wcS * 64 + qrS + 8] = rsum1;
    }
    __syncthreads();
    if (tid < 64) invS[tid] = 1.f / (rsPart[tid] + rsPart[64 + tid]);
    __syncthreads();

    // ---- write O (tf32 sigma layout for proj) ----
    const float i0 = invS[qrP], i1 = invS[qrP + 8], i2 = invS[qrP + 16], i3 = invS[qrP + 24];
    uint32_t* o0 = g_o + ((size_t)(b * N + nt_blk * 64 + qrP)) * C + h * DV;
    uint32_t* o1 = o0 + (size_t)8 * C;
    uint32_t* o2 = o0 + (size_t)16 * C;
    uint32_t* o3 = o0 + (size_t)24 * C;
#pragma unroll
    for (int nt = 0; nt < 4; nt++) {
        const int pos = wcP * 32 + nt * 8 + smap;
        o0[pos]     = f2tf32(o_acc[nt][0][0] * i0);
        o0[pos + 2] = f2tf32(o_acc[nt][0][1] * i0);
        o1[pos]     = f2tf32(o_acc[nt][0][2] * i1);
        o1[pos + 2] = f2tf32(o_acc[nt][0][3] * i1);
        o2[pos]     = f2tf32(o_acc[nt][1][0] * i2);
        o2[pos + 2] = f2tf32(o_acc[nt][1][1] * i2);
        o3[pos]     = f2tf32(o_acc[nt][1][2] * i3);
        o3[pos + 2] = f2tf32(o_acc[nt][1][3] * i3);
    }
}

// ---------------------------------------------------------------------------
// Kernel 3: output projection (tf32 mma).  CTA 64 rows x 256 cols.
// A side (g_o) already sigma tf32 -> plain copy; W side cvt at store.
// Output plain fp32 coalesced.
// ---------------------------------------------------------------------------
__global__ __launch_bounds__(256) void proj4_kernel(
    const float* __restrict__ Wproj, float* __restrict__ out)
{
    extern __shared__ char smem[];
    uint32_t* Xu = (uint32_t*)(smem + QKV_XS);
    uint32_t* Wu = (uint32_t*)(smem + QKV_WS);

    const int r0 = blockIdx.x * 64;
    const int c0 = blockIdx.y * 256;
    const int tid = threadIdx.x;
    const int wid = tid >> 5, lane = tid & 31;
    const int rq = lane >> 2, tg = lane & 3;
    const int wy = wid & 1, wcq = wid >> 1;
    const int qr = wy * 32 + rq;

    float acc[8][2][4];
#pragma unroll
    for (int a = 0; a < 8; a++)
#pragma unroll
        for (int m2 = 0; m2 < 2; m2++)
#pragma unroll
            for (int j = 0; j < 4; j++) acc[a][m2][j] = 0.f;

    for (int kc = 0; kc < 8; kc++) {
        // A chunk 64 x 64 (already sigma, uint4 copy)
#pragma unroll
        for (int t = 0; t < 4; t++) {
            int i = tid + t * 256;
            int r = i >> 4, c16 = i & 15;
            *(uint4*)(Xu + r * 68 + c16 * 4) =
                *(const uint4*)(g_o + (size_t)(r0 + r) * C + kc * 64 + c16 * 4);
        }
        // W chunk 256 x 64 (fp32 -> tf32 sigma)
#pragma unroll
        for (int t = 0; t < 16; t++) {
            int i = tid + t * 256;
            int r = i >> 4, cc = (i & 15) * 4;
            float4 v = *(const float4*)(Wproj + (size_t)(c0 + r) * C + kc * 64 + cc);
            st_sigma4(Wu + r * 68, cc, v);
        }
        __syncthreads();
#pragma unroll
        for (int ks = 0; ks < 8; ks++) {
            const int ko = ks * 8 + 2 * tg;
            uint2 aA = *(const uint2*)(Xu + qr * 68 + ko);
            uint2 aB = *(const uint2*)(Xu + (qr + 8) * 68 + ko);
            uint2 aC = *(const uint2*)(Xu + (qr + 16) * 68 + ko);
            uint2 aD = *(const uint2*)(Xu + (qr + 24) * 68 + ko);
#pragma unroll
            for (int nt = 0; nt < 8; nt++) {
                uint2 bb = *(const uint2*)(Wu + (wcq * 64 + nt * 8 + rq) * 68 + ko);
                mma_tf32(acc[nt][0], aA.x, aB.x, aA.y, aB.y, bb.x, bb.y);
                mma_tf32(acc[nt][1], aC.x, aD.x, aC.y, aD.y, bb.x, bb.y);
            }
        }
        __syncthreads();
    }

#pragma unroll
    for (int r = 0; r < 4; r++) {
        const int row = qr + r * 8;
        float* o = out + (size_t)(r0 + row) * C + c0;
        const int m2 = r >> 1, lo = (r & 1) * 2;
#pragma unroll
        for (int nt = 0; nt < 8; nt++) {
            const int col = wcq * 64 + nt * 8 + 2 * tg;
            *(float2*)(o + col) = make_float2(acc[nt][m2][lo + 0], acc[nt][m2][lo + 1]);
        }
    }
}

// ---------------------------------------------------------------------------
extern "C" void kernel_launch(void* const* d_in, const int* in_sizes, int n_in,
                              void* d_out, int out_size)
{
    const float* x      = (const float*)d_in[0];
    const float* ctx    = (const float*)d_in[1];
    const float* Wqkv   = (const float*)d_in[2];
    const float* Wproj  = (const float*)d_in[3];
    const float* radius = (const float*)d_in[4];
    float* out = (float*)d_out;
    (void)in_sizes; (void)n_in; (void)out_size;

    cudaFuncSetAttribute(qkv4_kernel, cudaFuncAttributeMaxDynamicSharedMemorySize, QKV_SMEM);
    cudaFuncSetAttribute(attn4_kernel, cudaFuncAttributeMaxDynamicSharedMemorySize, ATT_SMEM);
    cudaFuncSetAttribute(proj4_kernel, cudaFuncAttributeMaxDynamicSharedMemorySize, QKV_SMEM);

    // pre-pass: arrange V^T tiles (tf32 sigma)
    v_arrange_kernel<<<B * M, 128>>>(ctx);

    // 1) QKV + per-head L2 norm -> g_qn/g_kn (tf32 sigma)
    qkv4_kernel<<<dim3((B * N) / 64, H, 2), 256, QKV_SMEM>>>(x, ctx, Wqkv, radius);

    // 2) attention -> g_o (tf32 sigma)
    attn4_kernel<<<dim3(N / 64, H, B), 256, ATT_SMEM>>>();

    // 3) output projection -> fp32 out
    proj4_kernel<<<dim3((B * N) / 64, C / 256), 256, QKV_SMEM>>>(Wproj, out);
}

// round 10
// speedup vs baseline: 1.5319x; 1.3766x over previous
#include <cuda_runtime.h>
#include <math.h>
#include <stdint.h>

#define B 4
#define N 2048
#define M 2048
#define C 512
#define H 4
#define DV 128
#define DQK 256

// scratch (R4 layout: plain fp32, coalesced)
__device__ __align__(16) float g_qn[B * H * N * DQK];   // 32 MB
__device__ __align__(16) float g_kn[B * H * M * DQK];   // 32 MB
__device__ __align__(16) float g_o [B * N * C];         // 16 MB

// ============================================================================
// tf32 mma.sync helpers
// ============================================================================
__device__ __forceinline__ uint32_t f2tf32(float f) {
    uint32_t u;
    asm("cvt.rna.tf32.f32 %0, %1;" : "=r"(u) : "f"(f));
    return u;
}
__device__ __forceinline__ uint4 cvt4(float4 v) {
    uint4 u;
    u.x = f2tf32(v.x); u.y = f2tf32(v.y); u.z = f2tf32(v.z); u.w = f2tf32(v.w);
    return u;
}
__device__ __forceinline__ void mma_tf32(float* c,
                                         uint32_t a0, uint32_t a1, uint32_t a2, uint32_t a3,
                                         uint32_t b0, uint32_t b1) {
    asm volatile(
        "mma.sync.aligned.m16n8k8.row.col.f32.tf32.tf32.f32 "
        "{%0,%1,%2,%3}, {%4,%5,%6,%7}, {%8,%9}, {%0,%1,%2,%3};"
        : "+f"(c[0]), "+f"(c[1]), "+f"(c[2]), "+f"(c[3])
        : "r"(a0), "r"(a1), "r"(a2), "r"(a3), "r"(b0), "r"(b1));
}

// ---------------------------------------------------------------------------
// Kernel 1: fused QKV projection + per-head L2 norm * radius, tf32 mma.
// CTA = 64 src rows x 256 out cols (one head). k = 512 streamed in 64-chunks.
// 8 warps: wr = wid&3 -> 16 rows, wc = wid>>2 -> 128 cols (16 n8-tiles).
// ---------------------------------------------------------------------------
#define QKV_XS   0                    // 64 x 68 u32
#define QKV_WS   (64 * 68)            // 256 x 68 u32
#define QKV_SS   (QKV_WS + 256 * 68)  // 2 x 64 floats
#define QKV_SMEM ((QKV_SS + 128) * 4)

__global__ __launch_bounds__(256) void qkv_mma_kernel(
    const float* __restrict__ x, const float* __restrict__ ctx,
    const float* __restrict__ Wqkv, const float* __restrict__ radius)
{
    extern __shared__ float sm[];
    uint32_t* Xu = (uint32_t*)(sm + QKV_XS);
    uint32_t* Wu = (uint32_t*)(sm + QKV_WS);
    float* ssPart = sm + QKV_SS;

    const float* src = (blockIdx.z == 0) ? x : ctx;
    float* dst = (blockIdx.z == 0) ? g_qn : g_kn;
    const int h  = blockIdx.y;
    const int r0 = blockIdx.x * 64;
    const int tid = threadIdx.x;
    const int wid = tid >> 5;
    const int lane = tid & 31;
    const int wr = wid & 3;
    const int wc = wid >> 2;
    const int qr = wr * 16 + (lane >> 2);
    const int tg = lane & 3;

    float acc[16][4];
#pragma unroll
    for (int i = 0; i < 16; i++)
#pragma unroll
        for (int j = 0; j < 4; j++) acc[i][j] = 0.f;

    for (int kc = 0; kc < 8; kc++) {
        // load X chunk: 64 x 64 (cvt + STS.128)
#pragma unroll
        for (int t = 0; t < 4; t++) {
            int i = tid + t * 256;
            int r = i >> 4, cc = (i & 15) * 4;
            float4 v = *(const float4*)(src + (size_t)(r0 + r) * C + kc * 64 + cc);
            *(uint4*)(Xu + r * 68 + cc) = cvt4(v);
        }
        // load W chunk: 256 x 64
#pragma unroll
        for (int t = 0; t < 16; t++) {
            int i = tid + t * 256;
            int r = i >> 4, cc = (i & 15) * 4;
            float4 v = *(const float4*)(Wqkv + (size_t)(h * 256 + r) * C + kc * 64 + cc);
            *(uint4*)(Wu + r * 68 + cc) = cvt4(v);
        }
        __syncthreads();

#pragma unroll
        for (int ks = 0; ks < 8; ks++) {
            const int c = ks * 8 + tg;
            uint32_t a0 = Xu[qr * 68 + c];
            uint32_t a1 = Xu[(qr + 8) * 68 + c];
            uint32_t a2 = Xu[qr * 68 + c + 4];
            uint32_t a3 = Xu[(qr + 8) * 68 + c + 4];
#pragma unroll
            for (int nt = 0; nt < 16; nt++) {
                int n0 = wc * 128 + nt * 8 + (lane >> 2);
                uint32_t b0 = Wu[n0 * 68 + c];
                uint32_t b1 = Wu[n0 * 68 + c + 4];
                mma_tf32(acc[nt], a0, a1, a2, a3, b0, b1);
            }
        }
        __syncthreads();
    }

    // per-row sum of squares over this thread's 32 cols (x2 rows)
    float ss0 = 0.f, ss1 = 0.f;
#pragma unroll
    for (int nt = 0; nt < 16; nt++) {
        ss0 += acc[nt][0] * acc[nt][0] + acc[nt][1] * acc[nt][1];
        ss1 += acc[nt][2] * acc[nt][2] + acc[nt][3] * acc[nt][3];
    }
#pragma unroll
    for (int o = 1; o < 4; o <<= 1) {
        ss0 += __shfl_xor_sync(0xffffffffu, ss0, o);
        ss1 += __shfl_xor_sync(0xffffffffu, ss1, o);
    }
    if (tg == 0) {
        ssPart[wc * 64 + qr] = ss0;
        ssPart[wc * 64 + qr + 8] = ss1;
    }
    __syncthreads();

    const float rad = radius[h];
    const float sc0 = rad / fmaxf(sqrtf(ssPart[qr] + ssPart[64 + qr]), 1e-12f);
    const float sc1 = rad / fmaxf(sqrtf(ssPart[qr + 8] + ssPart[64 + qr + 8]), 1e-12f);

    {
        const int gr0 = r0 + qr;
        const int b0i = gr0 >> 11, n0i = gr0 & 2047;
        const int gr1 = gr0 + 8;
        const int b1i = gr1 >> 11, n1i = gr1 & 2047;
        float* o0 = dst + ((size_t)(b0i * H + h) * N + n0i) * DQK;
        float* o1 = dst + ((size_t)(b1i * H + h) * N + n1i) * DQK;
#pragma unroll
        for (int nt = 0; nt < 16; nt++) {
            const int col = wc * 128 + nt * 8 + 2 * tg;
            *(float2*)(o0 + col) = make_float2(acc[nt][0] * sc0, acc[nt][1] * sc0);
            *(float2*)(o1 + col) = make_float2(acc[nt][2] * sc1, acc[nt][3] * sc1);
        }
    }
}

// ---------------------------------------------------------------------------
// Kernel 2: attention via tf32 mma.sync, one-pass softmax (static shift).
// CTA = 64 queries of one (b,h). Stream 64-key tiles.
// S phase: 8 warps 4x2 (16 rows x 32 cols). PV phase: 4x2 (16 rows x 64 cols).
// ---------------------------------------------------------------------------
#define ATT_QS   0                          // 64 x 260
#define ATT_KS   (64 * 260)                 // 64 x 260
#define ATT_VS   (ATT_KS + 64 * 260)        // 64 x 136
#define ATT_PS   (ATT_VS + 64 * 136)        // 64 x 68
#define ATT_RS   (ATT_PS + 64 * 68)         // 2 x 64
#define ATT_SMEM ((ATT_RS + 128) * 4)

__global__ __launch_bounds__(256) void attn_mma_kernel(const float* __restrict__ ctx)
{
    extern __shared__ float sm[];
    uint32_t* Qu = (uint32_t*)(sm + ATT_QS);
    uint32_t* Ku = (uint32_t*)(sm + ATT_KS);
    uint32_t* Vu = (uint32_t*)(sm + ATT_VS);
    uint32_t* Pu = (uint32_t*)(sm + ATT_PS);
    float* rsPart = sm + ATT_RS;

    const int nt_blk = blockIdx.x;
    const int h  = blockIdx.y;
    const int b  = blockIdx.z;
    const int tid = threadIdx.x;
    const int wid = tid >> 5;
    const int lane = tid & 31;
    const int wr = wid & 3;
    const int wc = wid >> 2;
    const int qr = wr * 16 + (lane >> 2);
    const int tg = lane & 3;

    const float* qbase = g_qn + ((size_t)(b * H + h) * N + nt_blk * 64) * DQK;
    const float* kbase = g_kn + ((size_t)(b * H + h) * M) * DQK;
    const float* vbase = ctx + (size_t)b * M * C + h * DV;

    // Q tile -> smem (cvt + STS.128)
#pragma unroll
    for (int t = 0; t < 16; t++) {
        int i = tid + t * 256;
        int r = i >> 6, cc = (i & 63) * 4;
        float4 v = *(const float4*)(qbase + (size_t)r * DQK + cc);
        *(uint4*)(Qu + r * 260 + cc) = cvt4(v);
    }

    float o_acc[8][4];
#pragma unroll
    for (int i = 0; i < 8; i++)
#pragma unroll
        for (int j = 0; j < 4; j++) o_acc[i][j] = 0.f;
    float rsum0 = 0.f, rsum1 = 0.f;

    const float SCALE = 0.08838834764831845f;  // 1/sqrt(128)
    const float SMAX  = 11.313708498984761f;   // sqrt(128)

    for (int mt = 0; mt < M / 64; mt++) {
        // load K tile 64 x 256 (cvt + STS.128)
#pragma unroll
        for (int t = 0; t < 16; t++) {
            int i = tid + t * 256;
            int r = i >> 6, cc = (i & 63) * 4;
            float4 v = *(const float4*)(kbase + (size_t)(mt * 64 + r) * DQK + cc);
            *(uint4*)(Ku + r * 260 + cc) = cvt4(v);
        }
        // load V tile 64 x 128 (cvt + STS.128)
#pragma unroll
        for (int t = 0; t < 8; t++) {
            int i = tid + t * 256;
            int r = i >> 5, cc = (i & 31) * 4;
            float4 v = *(const float4*)(vbase + (size_t)(mt * 64 + r) * C + cc);
            *(uint4*)(Vu + r * 136 + cc) = cvt4(v);
        }
        __syncthreads();

        // ---- S = Q K^T : warp tile 16 rows x 32 cols, k = 256 ----
        float s[4][4];
#pragma unroll
        for (int i = 0; i < 4; i++)
#pragma unroll
            for (int j = 0; j < 4; j++) s[i][j] = 0.f;
#pragma unroll
        for (int ks = 0; ks < 32; ks++) {
            const int c = ks * 8 + tg;
            uint32_t a0 = Qu[qr * 260 + c];
            uint32_t a1 = Qu[(qr + 8) * 260 + c];
            uint32_t a2 = Qu[qr * 260 + c + 4];
            uint32_t a3 = Qu[(qr + 8) * 260 + c + 4];
#pragma unroll
            for (int nt = 0; nt < 4; nt++) {
                int n0 = wc * 32 + nt * 8 + (lane >> 2);
                uint32_t b0 = Ku[n0 * 260 + c];
                uint32_t b1 = Ku[n0 * 260 + c + 4];
                mma_tf32(s[nt], a0, a1, a2, a3, b0, b1);
            }
        }

        // ---- softmax epilogue -> P (tf32) in smem ----
#pragma unroll
        for (int nt = 0; nt < 4; nt++) {
            float p0 = __expf(fmaf(s[nt][0], SCALE, -SMAX));
            float p1 = __expf(fmaf(s[nt][1], SCALE, -SMAX));
            float p2 = __expf(fmaf(s[nt][2], SCALE, -SMAX));
            float p3 = __expf(fmaf(s[nt][3], SCALE, -SMAX));
            rsum0 += p0 + p1;
            rsum1 += p2 + p3;
            const int col = wc * 32 + nt * 8 + 2 * tg;
            uint2 w0 = make_uint2(f2tf32(p0), f2tf32(p1));
            uint2 w1 = make_uint2(f2tf32(p2), f2tf32(p3));
            *(uint2*)(Pu + qr * 68 + col) = w0;
            *(uint2*)(Pu + (qr + 8) * 68 + col) = w1;
        }
        __syncthreads();

        // ---- O += P V : warp tile 16 rows x 64 cols, k = 64 ----
#pragma unroll
        for (int ks = 0; ks < 8; ks++) {
            const int c = ks * 8 + tg;
            uint32_t a0 = Pu[qr * 68 + c];
            uint32_t a1 = Pu[(qr + 8) * 68 + c];
            uint32_t a2 = Pu[qr * 68 + c + 4];
            uint32_t a3 = Pu[(qr + 8) * 68 + c + 4];
#pragma unroll
            for (int nt = 0; nt < 8; nt++) {
                int n0 = wc * 64 + nt * 8 + (lane >> 2);
                uint32_t b0 = Vu[c * 136 + n0];            // row k = c
                uint32_t b1 = Vu[(c + 4) * 136 + n0];      // row k = c+4
                mma_tf32(o_acc[nt], a0, a1, a2, a3, b0, b1);
            }
        }
        __syncthreads();
    }

    // ---- row-sum reduction: quad, then across the two wc halves ----
#pragma unroll
    for (int o = 1; o < 4; o <<= 1) {
        rsum0 += __shfl_xor_sync(0xffffffffu, rsum0, o);
        rsum1 += __shfl_xor_sync(0xffffffffu, rsum1, o);
    }
    if (tg == 0) {
        rsPart[wc * 64 + qr] = rsum0;
        rsPart[wc * 64 + qr + 8] = rsum1;
    }
    __syncthreads();
    const float inv0 = 1.f / (rsPart[qr] + rsPart[64 + qr]);
    const float inv1 = 1.f / (rsPart[qr + 8] + rsPart[64 + qr + 8]);

    // ---- write O (fp32, coalesced float2) ----
    {
        const int n0g = nt_blk * 64 + qr;
        float* o0 = g_o + ((size_t)(b * N + n0g)) * C + h * DV;
        float* o1 = g_o + ((size_t)(b * N + n0g + 8)) * C + h * DV;
#pragma unroll
        for (int nt = 0; nt < 8; nt++) {
            const int col = wc * 64 + nt * 8 + 2 * tg;
            *(float2*)(o0 + col) = make_float2(o_acc[nt][0] * inv0, o_acc[nt][1] * inv0);
            *(float2*)(o1 + col) = make_float2(o_acc[nt][2] * inv1, o_acc[nt][3] * inv1);
        }
    }
}

// ---------------------------------------------------------------------------
// Kernel 3: output projection, tf32 mma (qkv structure minus norm).
// CTA = 64 rows x 256 cols; k = 512 in 8 chunks; grid (BN/64, C/256).
// ---------------------------------------------------------------------------
__global__ __launch_bounds__(256) void proj_tc_kernel(
    const float* __restrict__ Wproj, float* __restrict__ out)
{
    extern __shared__ float sm[];
    uint32_t* Xu = (uint32_t*)(sm + QKV_XS);
    uint32_t* Wu = (uint32_t*)(sm + QKV_WS);

    const int r0 = blockIdx.x * 64;
    const int c0 = blockIdx.y * 256;
    const int tid = threadIdx.x;
    const int wid = tid >> 5;
    const int lane = tid & 31;
    const int wr = wid & 3;
    const int wc = wid >> 2;
    const int qr = wr * 16 + (lane >> 2);
    const int tg = lane & 3;

    float acc[16][4];
#pragma unroll
    for (int i = 0; i < 16; i++)
#pragma unroll
        for (int j = 0; j < 4; j++) acc[i][j] = 0.f;

    for (int kc = 0; kc < 8; kc++) {
#pragma unroll
        for (int t = 0; t < 4; t++) {
            int i = tid + t * 256;
            int r = i >> 4, cc = (i & 15) * 4;
            float4 v = *(const float4*)(g_o + (size_t)(r0 + r) * C + kc * 64 + cc);
            *(uint4*)(Xu + r * 68 + cc) = cvt4(v);
        }
#pragma unroll
        for (int t = 0; t < 16; t++) {
            int i = tid + t * 256;
            int r = i >> 4, cc = (i & 15) * 4;
            float4 v = *(const float4*)(Wproj + (size_t)(c0 + r) * C + kc * 64 + cc);
            *(uint4*)(Wu + r * 68 + cc) = cvt4(v);
        }
        __syncthreads();

#pragma unroll
        for (int ks = 0; ks < 8; ks++) {
            const int c = ks * 8 + tg;
            uint32_t a0 = Xu[qr * 68 + c];
            uint32_t a1 = Xu[(qr + 8) * 68 + c];
            uint32_t a2 = Xu[qr * 68 + c + 4];
            uint32_t a3 = Xu[(qr + 8) * 68 + c + 4];
#pragma unroll
            for (int nt = 0; nt < 16; nt++) {
                int n0 = wc * 128 + nt * 8 + (lane >> 2);
                uint32_t b0 = Wu[n0 * 68 + c];
                uint32_t b1 = Wu[n0 * 68 + c + 4];
                mma_tf32(acc[nt], a0, a1, a2, a3, b0, b1);
            }
        }
        __syncthreads();
    }

    {
        float* o0 = out + (size_t)(r0 + qr) * C + c0;
        float* o1 = out + (size_t)(r0 + qr + 8) * C + c0;
#pragma unroll
        for (int nt = 0; nt < 16; nt++) {
            const int col = wc * 128 + nt * 8 + 2 * tg;
            *(float2*)(o0 + col) = make_float2(acc[nt][0], acc[nt][1]);
            *(float2*)(o1 + col) = make_float2(acc[nt][2], acc[nt][3]);
        }
    }
}

// ---------------------------------------------------------------------------
extern "C" void kernel_launch(void* const* d_in, const int* in_sizes, int n_in,
                              void* d_out, int out_size)
{
    const float* x      = (const float*)d_in[0];
    const float* ctx    = (const float*)d_in[1];
    const float* Wqkv   = (const float*)d_in[2];
    const float* Wproj  = (const float*)d_in[3];
    const float* radius = (const float*)d_in[4];
    float* out = (float*)d_out;

    (void)in_sizes; (void)n_in; (void)out_size;

    cudaFuncSetAttribute(qkv_mma_kernel,
                         cudaFuncAttributeMaxDynamicSharedMemorySize, QKV_SMEM);
    cudaFuncSetAttribute(attn_mma_kernel,
                         cudaFuncAttributeMaxDynamicSharedMemorySize, ATT_SMEM);
    cudaFuncSetAttribute(proj_tc_kernel,
                         cudaFuncAttributeMaxDynamicSharedMemorySize, QKV_SMEM);

    // 1) QKV projection + per-head L2 norm (x -> g_qn, context -> g_kn)
    qkv_mma_kernel<<<dim3((B * N) / 64, H, 2), 256, QKV_SMEM>>>(x, ctx, Wqkv, radius);

    // 2) attention per (b,h), 64-query tiles, tf32 mma.sync
    attn_mma_kernel<<<dim3(N / 64, H, B), 256, ATT_SMEM>>>(ctx);

    // 3) output projection (tf32 mma)
    proj_tc_kernel<<<dim3((B * N) / 64, C / 256), 256, QKV_SMEM>>>(Wproj, out);
}